// round 13
// baseline (speedup 1.0000x reference)
#include <cuda_runtime.h>
#include <math.h>

#define B_    1024
#define D_    8
#define P_    128
#define NPTS  1024
#define H_    256
#define W_    256
#define NTHREADS 256

#define GRAVITY     9.8f
#define DT          0.01f
#define TORQUE_LIM  200.0f
#define K_STIFF     5000.0f
#define K_LON       0.5f
#define K_LAT       0.5f
#define BODY_MASS   40.0f
#define MAX_COORD   6.4f
#define IC_SCALE    (-57.73502691896258f)   /* -sqrt(3)/SIGMA */
#define UV_SCALE    19.921875f              /* (W-1)/(2*MAX_COORD) */

// output offsets (floats)
#define OFF_NX   0
#define OFF_NXD  3072
#define OFF_NQ   6144
#define OFF_NOM  10240
#define OFF_NTH  13312
#define OFF_XDD  21504
#define OFF_OMD  24576
#define OFF_THD  27648
#define OFF_FS   35840
#define OFF_FF   3181568
#define OFF_IC   6327296
#define OFF_TQ   7375872
#define OFF_RP   7378944
#define OFF_THR  10524672

__device__ __forceinline__ float warp_sum(float v) {
#pragma unroll
    for (int o = 16; o; o >>= 1) v += __shfl_xor_sync(0xffffffffu, v, o);
    return v;
}

__device__ __forceinline__ float tanh_fast(float x) {
    float y;
    asm("tanh.approx.f32 %0, %1;" : "=f"(y) : "f"(x));
    return y;
}

__global__ __launch_bounds__(NTHREADS, 4)
void phys_kernel(const float* __restrict__ x_in,
                 const float* __restrict__ xd_in,
                 const float* __restrict__ q_in,
                 const float* __restrict__ om_in,
                 const float* __restrict__ th_in,
                 const float* __restrict__ ctrl_in,
                 const float* __restrict__ zg_in,
                 const float* __restrict__ zgg_in,
                 const float* __restrict__ jp_in,
                 const float* __restrict__ jlp_in,
                 const float* __restrict__ jlc_in,
                 const float* __restrict__ dpi_in,
                 const float* __restrict__ dpm_in,
                 const float* __restrict__ bcog_in,
                 const float* __restrict__ binert_in,
                 const float* __restrict__ ddir_in,
                 float* __restrict__ out)
{
    const int b   = blockIdx.x;
    const int tid = threadIdx.x;
    const int w   = tid >> 5;

    // per-point staging (26 KB total smem): rp(3), gx, gy, dh
    __shared__ float s_rp[3][NPTS];
    __shared__ float s_gx[NPTS], s_gy[NPTS], s_dh[NPTS];

    __shared__ float sR[9];
    __shared__ float s_c[D_], s_sn[D_];
    __shared__ float s_jp[D_][3];
    __shared__ float s_cogl[D_][3];
    __shared__ float s_rotI[D_][9];
    __shared__ float s_tl[D_][3];
    __shared__ float s_thr[D_][3];
    __shared__ float s_Iov[9], s_M9[9];
    __shared__ float s_gcog[3], s_gdd[3], s_inertia[9];
    __shared__ float s_x[3], s_xd[3], s_om[3];
    __shared__ float s_tm;
    __shared__ float s_red[48];

    // ------------------ Phase 0a: per-part prep ------------------
    if (tid < D_) {
        const int d = tid;
        const float th = th_in[b * D_ + d];
        const float c = cosf(th), s = sinf(th);
        s_c[d] = c; s_sn[d] = s;
        const float jpx = jp_in[d*3+0], jpy = jp_in[d*3+1], jpz = jp_in[d*3+2];
        s_jp[d][0] = jpx; s_jp[d][1] = jpy; s_jp[d][2] = jpz;
        const float lx = jlc_in[d*3+0], ly = jlc_in[d*3+1], lz = jlc_in[d*3+2];
        s_cogl[d][0] =  c*lx + s*lz + jpx;
        s_cogl[d][1] =  ly + jpy;
        s_cogl[d][2] = -s*lx + c*lz + jpz;
        float I9[9];
#pragma unroll
        for (int k = 0; k < 9; k++) I9[k] = dpi_in[d*9 + k];
        float M[9];
        M[0] =  c*I9[0] + s*I9[6];  M[1] =  c*I9[1] + s*I9[7];  M[2] =  c*I9[2] + s*I9[8];
        M[3] =  I9[3];              M[4] =  I9[4];              M[5] =  I9[5];
        M[6] = -s*I9[0] + c*I9[6];  M[7] = -s*I9[1] + c*I9[7];  M[8] = -s*I9[2] + c*I9[8];
#pragma unroll
        for (int r = 0; r < 3; r++) {
            s_rotI[d][r*3+0] =  M[r*3+0]*c + M[r*3+2]*s;
            s_rotI[d][r*3+1] =  M[r*3+1];
            s_rotI[d][r*3+2] = -M[r*3+0]*s + M[r*3+2]*c;
        }
        const float dx = ddir_in[0], dy = ddir_in[1], dz = ddir_in[2];
        const float vc = ctrl_in[b*2*D_ + d];
        s_tl[d][0] = ( c*dx + s*dz) * vc;
        s_tl[d][1] = ( dy          ) * vc;
        s_tl[d][2] = (-s*dx + c*dz) * vc;
        float td = ctrl_in[b*2*D_ + D_ + d];
        td = fminf(fmaxf(td, -0.5f), 0.5f);
        out[OFF_THD + (size_t)b*D_ + d] = td;
        float nth = th + td * DT;
        out[OFF_NTH + (size_t)b*D_ + d] = fminf(fmaxf(nth, -1.0f), 1.0f);
    }
    if (tid == 8) {
        const float qw = q_in[b*4+0], qx = q_in[b*4+1], qy = q_in[b*4+2], qz = q_in[b*4+3];
        sR[0] = 1.0f - 2.0f*(qy*qy + qz*qz);
        sR[1] = 2.0f*(qx*qy - qw*qz);
        sR[2] = 2.0f*(qx*qz + qw*qy);
        sR[3] = 2.0f*(qx*qy + qw*qz);
        sR[4] = 1.0f - 2.0f*(qx*qx + qz*qz);
        sR[5] = 2.0f*(qy*qz - qw*qx);
        sR[6] = 2.0f*(qx*qz - qw*qy);
        sR[7] = 2.0f*(qy*qz + qw*qx);
        sR[8] = 1.0f - 2.0f*(qx*qx + qy*qy);
    }
    if (tid == 9) {
#pragma unroll
        for (int k = 0; k < 3; k++) {
            s_x[k]  = x_in[b*3+k];
            s_xd[k] = xd_in[b*3+k];
            s_om[k] = om_in[b*3+k];
        }
    }
    __syncthreads();

    // ------------------ Phase 0b: warp 0 only, overlapped with phase 1 ----
    if (tid < 32) {
        float m[D_];
        float tm = BODY_MASS;
#pragma unroll
        for (int d = 0; d < D_; d++) { m[d] = dpm_in[d]; tm += m[d]; }
        float cg0 = 0.f, cg1 = 0.f, cg2 = 0.f;
#pragma unroll
        for (int d = 0; d < D_; d++) {
            cg0 += s_cogl[d][0] * m[d];
            cg1 += s_cogl[d][1] * m[d];
            cg2 += s_cogl[d][2] * m[d];
        }
        const float bc0 = bcog_in[0], bc1 = bcog_in[1], bc2 = bcog_in[2];
        const float itm = 1.0f / tm;
        cg0 = (cg0 + BODY_MASS*bc0) * itm;
        cg1 = (cg1 + BODY_MASS*bc1) * itm;
        cg2 = (cg2 + BODY_MASS*bc2) * itm;

        if (tid < 24) {
            const int d = tid / 3, k = tid - 3*(tid/3);
            s_thr[d][k] = sR[k*3+0]*s_tl[d][0] + sR[k*3+1]*s_tl[d][1] + sR[k*3+2]*s_tl[d][2];
        }
        if (tid < 9) {
            const int r = tid / 3, c = tid - 3*(tid/3);
            float Iv = binert_in[tid];
#pragma unroll
            for (int d = 0; d < D_; d++) {
                const float ddx = s_cogl[d][0]-cg0, ddy = s_cogl[d][1]-cg1, ddz = s_cogl[d][2]-cg2;
                const float s2 = ddx*ddx + ddy*ddy + ddz*ddz;
                const float er = (r==0)?ddx:(r==1)?ddy:ddz;
                const float ec = (c==0)?ddx:(c==1)?ddy:ddz;
                Iv += s_rotI[d][tid] + m[d]*(((r==c)?s2:0.0f) - er*ec);
            }
            {
                const float ddx = bc0-cg0, ddy = bc1-cg1, ddz = bc2-cg2;
                const float s2 = ddx*ddx + ddy*ddy + ddz*ddz;
                const float er = (r==0)?ddx:(r==1)?ddy:ddz;
                const float ec = (c==0)?ddx:(c==1)?ddy:ddz;
                Iv += BODY_MASS*(((r==c)?s2:0.0f) - er*ec);
            }
            s_Iov[tid] = Iv;
        }
        if (tid >= 9 && tid < 12) {
            const int k = tid - 9;
            s_gcog[k] = sR[k*3+0]*cg0 + sR[k*3+1]*cg1 + sR[k*3+2]*cg2 + s_x[k];
        }
        if (tid >= 12 && tid < 15) {
            const int k = tid - 12;
            s_gdd[k] = sR[k*3+0]*ddir_in[0] + sR[k*3+1]*ddir_in[1] + sR[k*3+2]*ddir_in[2];
        }
        if (tid == 15) s_tm = tm;
        __syncwarp();
        if (tid < 9) {
            const int r = tid / 3, c = tid - 3*(tid/3);
            s_M9[tid] = sR[r*3+0]*s_Iov[c] + sR[r*3+1]*s_Iov[3+c] + sR[r*3+2]*s_Iov[6+c];
        }
        __syncwarp();
        if (tid < 9) {
            const int r = tid / 3, c = tid - 3*(tid/3);
            s_inertia[tid] = s_M9[r*3+0]*sR[c*3+0] + s_M9[r*3+1]*sR[c*3+1] + s_M9[r*3+2]*sR[c*3+2];
        }
    }

    // ------------------ Phase 1: points, terrain sample ------------------
    const float* __restrict__ zg  = zg_in  + (size_t)b * (H_*W_);
    const float* __restrict__ zgx = zgg_in + (size_t)b * (2*H_*W_);
    const float* __restrict__ zgy = zgx + H_*W_;

    float icsum = 0.0f;
#pragma unroll
    for (int k = 0; k < NPTS/NTHREADS; k++) {
        const int i = tid + k * NTHREADS;
        const int d = i >> 7;
        const float* jl = jlp_in + (size_t)i * 3;
        const float jx = jl[0], jy = jl[1], jz = jl[2];
        const float c = s_c[d], s = s_sn[d];
        const float plx =  c*jx + s*jz + s_jp[d][0];
        const float ply =  jy          + s_jp[d][1];
        const float plz = -s*jx + c*jz + s_jp[d][2];
        const float rx = sR[0]*plx + sR[1]*ply + sR[2]*plz + s_x[0];
        const float ry = sR[3]*plx + sR[4]*ply + sR[5]*plz + s_x[1];
        const float rz = sR[6]*plx + sR[7]*ply + sR[8]*plz + s_x[2];
        s_rp[0][i] = rx; s_rp[1][i] = ry; s_rp[2][i] = rz;

        const size_t p3 = ((size_t)b * NPTS + i) * 3;
        out[OFF_RP + p3 + 0] = rx;
        out[OFF_RP + p3 + 1] = ry;
        out[OFF_RP + p3 + 2] = rz;

        float u = (rx + MAX_COORD) * UV_SCALE;
        float v = (ry + MAX_COORD) * UV_SCALE;
        u = fminf(fmaxf(u, 0.0f), (float)(W_-1) - 1e-5f);
        v = fminf(fmaxf(v, 0.0f), (float)(H_-1) - 1e-5f);
        const int u0 = (int)floorf(u), v0 = (int)floorf(v);
        const float fu = u - (float)u0, fv = v - (float)v0;
        const int i00 = v0*W_ + u0;
        const int i10 = i00 + W_;

        const float z00 = __ldg(zg + i00),  z01 = __ldg(zg + i00 + 1);
        const float z10 = __ldg(zg + i10),  z11 = __ldg(zg + i10 + 1);
        const float x00 = __ldg(zgx + i00), x01 = __ldg(zgx + i00 + 1);
        const float x10 = __ldg(zgx + i10), x11 = __ldg(zgx + i10 + 1);
        const float y00 = __ldg(zgy + i00), y01 = __ldg(zgy + i00 + 1);
        const float y10 = __ldg(zgy + i10), y11 = __ldg(zgy + i10 + 1);

        const float gu = 1.0f - fu, gv = 1.0f - fv;
        const float zs = (z00*gu + z01*fu)*gv + (z10*gu + z11*fu)*fv;
        const float gx = (x00*gu + x01*fu)*gv + (x10*gu + x11*fu)*fv;
        const float gy = (y00*gu + y01*fu)*gv + (y10*gu + y11*fu)*fv;

        // 1/(sqrt(ss)+1e-8) ≈ rsqrt(ss + 1e-16)  (rel diff ~1e-8)
        const float inv = rsqrtf(gx*gx + gy*gy + 1.0f + 1e-16f);
        const float dh = (rz - zs) * inv;           // nz == inv
        const float ic = 0.5f * (1.0f + tanh_fast(dh * IC_SCALE));

        s_gx[i] = gx; s_gy[i] = gy; s_dh[i] = dh;
        icsum += ic;
        out[OFF_IC + (size_t)b*NPTS + i] = ic;
    }

    {   // contact-count partials
        const float ws = warp_sum(icsum);
        const int lane = tid & 31;
        if (lane == 0) s_red[w] = ws;
    }
    __syncthreads();

    // all threads compute nc redundantly (one barrier total)
    float nc = 0.0f;
#pragma unroll
    for (int w8 = 0; w8 < 8; w8++) nc += s_red[w8];
    nc = fmaxf(nc, 1.0f);
    const float inv_nc = __fdividef(1.0f, nc);
    const float kd = sqrtf(s_tm * K_STIFF * inv_nc);   // DAMPING_ALPHA*2 = 1

    // ------------------ Phase 2: forces ------------------
    const float gddx = s_gdd[0], gddy = s_gdd[1], gddz = s_gdd[2];
    const float ox = s_om[0], oy = s_om[1], oz = s_om[2];
    const float gc0 = s_gcog[0], gc1 = s_gcog[1], gc2 = s_gcog[2];
    const float xd0 = s_xd[0], xd1 = s_xd[1], xd2 = s_xd[2];
    float asx=0.f, asy=0.f, asz=0.f, tqx=0.f, tqy=0.f, tqz=0.f;

#pragma unroll
    for (int k = 0; k < NPTS/NTHREADS; k++) {
        const int i = tid + k * NTHREADS;
        const int d = i >> 7;
        // recompute n, ic from staged {gx, gy, dh}
        const float gx = s_gx[i], gy = s_gy[i], dh = s_dh[i];
        const float invn = rsqrtf(gx*gx + gy*gy + 1.0f + 1e-16f);
        const float nx = -gx*invn, ny = -gy*invn, nz = invn;
        const float ic = 0.5f * (1.0f + tanh_fast(dh * IC_SCALE));

        const float ccx = s_rp[0][i] - gc0;
        const float ccy = s_rp[1][i] - gc1;
        const float ccz = s_rp[2][i] - gc2;
        const float vx = xd0 + oy*ccz - oz*ccy;
        const float vy = xd1 + oz*ccx - ox*ccz;
        const float vz = xd2 + ox*ccy - oy*ccx;
        const float xdn = vx*nx + vy*ny + vz*nz;
        const float coef = -(K_STIFF * (dh*ic) + kd * xdn) * ic * inv_nc;
        const float fsx = coef*nx, fsy = coef*ny, fsz = coef*nz;
        const float Nmag = fabsf(coef);       // ||coef * n||, |n| == 1

        const float gdn = gddx*nx + gddy*ny + gddz*nz;
        float fwx = gddx - gdn*nx, fwy = gddy - gdn*ny, fwz = gddz - gdn*nz;
        {
            const float iv = rsqrtf(fwx*fwx + fwy*fwy + fwz*fwz + 1e-16f);
            fwx *= iv; fwy *= iv; fwz *= iv;
        }
        float ltx = fwy*nz - fwz*ny;
        float lty = fwz*nx - fwx*nz;
        float ltz = fwx*ny - fwy*nx;
        {
            const float iv = rsqrtf(ltx*ltx + lty*lty + ltz*ltz + 1e-16f);
            ltx *= iv; lty *= iv; ltz *= iv;
        }
        const float thx = s_thr[d][0], thy = s_thr[d][1], thz = s_thr[d][2];
        const float dvx = thx - vx;
        const float dvy = thy - vy;
        const float dvz = thz - vz;
        const float dvn = dvx*nx + dvy*ny + dvz*nz;
        const float tx = tanh_fast(dvx - dvn*nx);
        const float ty = tanh_fast(dvy - dvn*ny);
        const float tz = tanh_fast(dvz - dvn*nz);
        const float lon = tx*fwx + ty*fwy + tz*fwz;
        const float lat = tx*ltx + ty*lty + tz*ltz;
        const float c1 = K_LON * Nmag * lon;
        const float c2 = K_LAT * Nmag * lat;
        const float ffx = c1*fwx + c2*ltx;
        const float ffy = c1*fwy + c2*lty;
        const float ffz = c1*fwz + c2*ltz;

        const float ax = fsx + ffx, ay = fsy + ffy, az = fsz + ffz;
        asx += ax; asy += ay; asz += az;
        tqx += ccy*az - ccz*ay;
        tqy += ccz*ax - ccx*az;
        tqz += ccx*ay - ccy*ax;

        const size_t p3 = ((size_t)b * NPTS + i) * 3;
        out[OFF_FS + p3 + 0] = fsx;
        out[OFF_FS + p3 + 1] = fsy;
        out[OFF_FS + p3 + 2] = fsz;
        out[OFF_FF + p3 + 0] = ffx;
        out[OFF_FF + p3 + 1] = ffy;
        out[OFF_FF + p3 + 2] = ffz;
        out[OFF_THR + p3 + 0] = thx;
        out[OFF_THR + p3 + 1] = thy;
        out[OFF_THR + p3 + 2] = thz;
    }

    {   // reduce 6 sums
        float r[6] = {asx, asy, asz, tqx, tqy, tqz};
        const int lane = tid & 31;
#pragma unroll
        for (int j = 0; j < 6; j++) {
            const float ws = warp_sum(r[j]);
            if (lane == 0) s_red[j*8 + w] = ws;
        }
    }
    __syncthreads();

    // ------------------ Phase 3: solve + integrate ------------------
    if (tid == 0) {
        float as0 = 0.f, as1 = 0.f, as2 = 0.f, t0 = 0.f, t1 = 0.f, t2 = 0.f;
#pragma unroll
        for (int w8 = 0; w8 < 8; w8++) {
            as0 += s_red[0*8 + w8]; as1 += s_red[1*8 + w8]; as2 += s_red[2*8 + w8];
            t0  += s_red[3*8 + w8]; t1  += s_red[4*8 + w8]; t2  += s_red[5*8 + w8];
        }
        const float tqcx = fminf(fmaxf(t0, -TORQUE_LIM), TORQUE_LIM);
        const float tqcy = fminf(fmaxf(t1, -TORQUE_LIM), TORQUE_LIM);
        const float tqcz = fminf(fmaxf(t2, -TORQUE_LIM), TORQUE_LIM);
        out[OFF_TQ + (size_t)b*3 + 0] = tqcx;
        out[OFF_TQ + (size_t)b*3 + 1] = tqcy;
        out[OFF_TQ + (size_t)b*3 + 2] = tqcz;

        const double a00=s_inertia[0], a01=s_inertia[1], a02=s_inertia[2];
        const double a10=s_inertia[3], a11=s_inertia[4], a12=s_inertia[5];
        const double a20=s_inertia[6], a21=s_inertia[7], a22=s_inertia[8];
        const double bx=tqcx, by=tqcy, bz=tqcz;
        const double c00 = a11*a22 - a12*a21;
        const double c01 = a10*a22 - a12*a20;
        const double c02 = a10*a21 - a11*a20;
        const double det = a00*c00 - a01*c01 + a02*c02;
        const double inv = 1.0/det;
        const double odx = (bx*c00 - a01*(by*a22 - a12*bz) + a02*(by*a21 - a11*bz)) * inv;
        const double ody = (a00*(by*a22 - a12*bz) - bx*c01 + a02*(a10*bz - by*a20)) * inv;
        const double odz = (a00*(a11*bz - by*a21) - a01*(a10*bz - by*a20) + bx*c02) * inv;
        const float odxf=(float)odx, odyf=(float)ody, odzf=(float)odz;
        out[OFF_OMD + (size_t)b*3 + 0] = odxf;
        out[OFF_OMD + (size_t)b*3 + 1] = odyf;
        out[OFF_OMD + (size_t)b*3 + 2] = odzf;

        const float itm = __fdividef(1.0f, s_tm);
        const float xddx = as0 * itm;
        const float xddy = as1 * itm;
        const float xddz = (as2 - s_tm*GRAVITY) * itm;
        out[OFF_XDD + (size_t)b*3 + 0] = xddx;
        out[OFF_XDD + (size_t)b*3 + 1] = xddy;
        out[OFF_XDD + (size_t)b*3 + 2] = xddz;

        const float nxd0 = s_xd[0] + xddx*DT;
        const float nxd1 = s_xd[1] + xddy*DT;
        const float nxd2 = s_xd[2] + xddz*DT;
        out[OFF_NXD + (size_t)b*3 + 0] = nxd0;
        out[OFF_NXD + (size_t)b*3 + 1] = nxd1;
        out[OFF_NXD + (size_t)b*3 + 2] = nxd2;
        out[OFF_NX + (size_t)b*3 + 0] = s_x[0] + nxd0*DT;
        out[OFF_NX + (size_t)b*3 + 1] = s_x[1] + nxd1*DT;
        out[OFF_NX + (size_t)b*3 + 2] = s_x[2] + nxd2*DT;

        const float no0 = s_om[0] + odxf*DT;
        const float no1 = s_om[1] + odyf*DT;
        const float no2 = s_om[2] + odzf*DT;
        out[OFF_NOM + (size_t)b*3 + 0] = no0;
        out[OFF_NOM + (size_t)b*3 + 1] = no1;
        out[OFF_NOM + (size_t)b*3 + 2] = no2;

        const float aw = q_in[b*4+0], axq = q_in[b*4+1], ayq = q_in[b*4+2], azq = q_in[b*4+3];
        const float h = 0.5f * DT;
        const float dqw = h * (-(axq*no0 + ayq*no1 + azq*no2));
        const float dqx = h * ( aw*no0 + ayq*no2 - azq*no1);
        const float dqy = h * ( aw*no1 - axq*no2 + azq*no0);
        const float dqz = h * ( aw*no2 + axq*no1 - ayq*no0);
        const float nqw = aw + dqw, nqx = axq + dqx, nqy = ayq + dqy, nqz = azq + dqz;
        const float qn = sqrtf(nqw*nqw + nqx*nqx + nqy*nqy + nqz*nqz);
        const float qi = __fdividef(1.0f, qn + 1e-8f);
        out[OFF_NQ + (size_t)b*4 + 0] = nqw*qi;
        out[OFF_NQ + (size_t)b*4 + 1] = nqx*qi;
        out[OFF_NQ + (size_t)b*4 + 2] = nqy*qi;
        out[OFF_NQ + (size_t)b*4 + 3] = nqz*qi;
    }
}

extern "C" void kernel_launch(void* const* d_in, const int* in_sizes, int n_in,
                              void* d_out, int out_size)
{
    phys_kernel<<<B_, NTHREADS>>>(
        (const float*)d_in[0],  (const float*)d_in[1],  (const float*)d_in[2],
        (const float*)d_in[3],  (const float*)d_in[4],  (const float*)d_in[5],
        (const float*)d_in[6],  (const float*)d_in[7],  (const float*)d_in[8],
        (const float*)d_in[9],  (const float*)d_in[10], (const float*)d_in[11],
        (const float*)d_in[12], (const float*)d_in[13], (const float*)d_in[14],
        (const float*)d_in[15], (float*)d_out);
}

// round 14
// speedup vs baseline: 1.0484x; 1.0484x over previous
#include <cuda_runtime.h>
#include <math.h>

#define B_    1024
#define D_    8
#define P_    128
#define NPTS  1024
#define H_    256
#define W_    256
#define NTHREADS 256

#define GRAVITY     9.8f
#define DT          0.01f
#define TORQUE_LIM  200.0f
#define K_STIFF     5000.0f
#define K_LON       0.5f
#define K_LAT       0.5f
#define BODY_MASS   40.0f
#define MAX_COORD   6.4f
#define IC_SCALE    (-57.73502691896258f)   /* -sqrt(3)/SIGMA */
#define UV_SCALE    19.921875f              /* (W-1)/(2*MAX_COORD) */

// output offsets (floats)
#define OFF_NX   0
#define OFF_NXD  3072
#define OFF_NQ   6144
#define OFF_NOM  10240
#define OFF_NTH  13312
#define OFF_XDD  21504
#define OFF_OMD  24576
#define OFF_THD  27648
#define OFF_FS   35840
#define OFF_FF   3181568
#define OFF_IC   6327296
#define OFF_TQ   7375872
#define OFF_RP   7378944
#define OFF_THR  10524672

__device__ __forceinline__ float warp_sum(float v) {
#pragma unroll
    for (int o = 16; o; o >>= 1) v += __shfl_xor_sync(0xffffffffu, v, o);
    return v;
}

__device__ __forceinline__ float tanh_fast(float x) {
    float y;
    asm("tanh.approx.f32 %0, %1;" : "=f"(y) : "f"(x));
    return y;
}

__global__ __launch_bounds__(NTHREADS, 4)
void phys_kernel(const float* __restrict__ x_in,
                 const float* __restrict__ xd_in,
                 const float* __restrict__ q_in,
                 const float* __restrict__ om_in,
                 const float* __restrict__ th_in,
                 const float* __restrict__ ctrl_in,
                 const float* __restrict__ zg_in,
                 const float* __restrict__ zgg_in,
                 const float* __restrict__ jp_in,
                 const float* __restrict__ jlp_in,
                 const float* __restrict__ jlc_in,
                 const float* __restrict__ dpi_in,
                 const float* __restrict__ dpm_in,
                 const float* __restrict__ bcog_in,
                 const float* __restrict__ binert_in,
                 const float* __restrict__ ddir_in,
                 float* __restrict__ out)
{
    const int b   = blockIdx.x;
    const int tid = threadIdx.x;
    const int w   = tid >> 5;

    // per-point staging (26 KB total smem): rp(3), gx, gy, dh
    __shared__ float s_rp[3][NPTS];
    __shared__ float s_gx[NPTS], s_gy[NPTS], s_dh[NPTS];

    __shared__ float sR[9];
    __shared__ float s_c[D_], s_sn[D_];
    __shared__ float s_jp[D_][3];
    __shared__ float s_cogl[D_][3];
    __shared__ float s_rotI[D_][9];
    __shared__ float s_tl[D_][3];
    __shared__ float s_thr[D_][3];
    __shared__ float s_Iov[9], s_M9[9];
    __shared__ float s_gcog[3], s_gdd[3], s_inertia[9];
    __shared__ float s_x[3], s_xd[3], s_om[3];
    __shared__ float s_tm;
    __shared__ float s_red[48];

    // ------------------ Phase 0a: per-part prep ------------------
    if (tid < D_) {
        const int d = tid;
        const float th = th_in[b * D_ + d];
        const float c = cosf(th), s = sinf(th);
        s_c[d] = c; s_sn[d] = s;
        const float jpx = jp_in[d*3+0], jpy = jp_in[d*3+1], jpz = jp_in[d*3+2];
        s_jp[d][0] = jpx; s_jp[d][1] = jpy; s_jp[d][2] = jpz;
        const float lx = jlc_in[d*3+0], ly = jlc_in[d*3+1], lz = jlc_in[d*3+2];
        s_cogl[d][0] =  c*lx + s*lz + jpx;
        s_cogl[d][1] =  ly + jpy;
        s_cogl[d][2] = -s*lx + c*lz + jpz;
        float I9[9];
#pragma unroll
        for (int k = 0; k < 9; k++) I9[k] = dpi_in[d*9 + k];
        float M[9];
        M[0] =  c*I9[0] + s*I9[6];  M[1] =  c*I9[1] + s*I9[7];  M[2] =  c*I9[2] + s*I9[8];
        M[3] =  I9[3];              M[4] =  I9[4];              M[5] =  I9[5];
        M[6] = -s*I9[0] + c*I9[6];  M[7] = -s*I9[1] + c*I9[7];  M[8] = -s*I9[2] + c*I9[8];
#pragma unroll
        for (int r = 0; r < 3; r++) {
            s_rotI[d][r*3+0] =  M[r*3+0]*c + M[r*3+2]*s;
            s_rotI[d][r*3+1] =  M[r*3+1];
            s_rotI[d][r*3+2] = -M[r*3+0]*s + M[r*3+2]*c;
        }
        const float dx = ddir_in[0], dy = ddir_in[1], dz = ddir_in[2];
        const float vc = ctrl_in[b*2*D_ + d];
        s_tl[d][0] = ( c*dx + s*dz) * vc;
        s_tl[d][1] = ( dy          ) * vc;
        s_tl[d][2] = (-s*dx + c*dz) * vc;
        float td = ctrl_in[b*2*D_ + D_ + d];
        td = fminf(fmaxf(td, -0.5f), 0.5f);
        out[OFF_THD + (size_t)b*D_ + d] = td;
        float nth = th + td * DT;
        out[OFF_NTH + (size_t)b*D_ + d] = fminf(fmaxf(nth, -1.0f), 1.0f);
    }
    if (tid == 8) {
        const float qw = q_in[b*4+0], qx = q_in[b*4+1], qy = q_in[b*4+2], qz = q_in[b*4+3];
        sR[0] = 1.0f - 2.0f*(qy*qy + qz*qz);
        sR[1] = 2.0f*(qx*qy - qw*qz);
        sR[2] = 2.0f*(qx*qz + qw*qy);
        sR[3] = 2.0f*(qx*qy + qw*qz);
        sR[4] = 1.0f - 2.0f*(qx*qx + qz*qz);
        sR[5] = 2.0f*(qy*qz - qw*qx);
        sR[6] = 2.0f*(qx*qz - qw*qy);
        sR[7] = 2.0f*(qy*qz + qw*qx);
        sR[8] = 1.0f - 2.0f*(qx*qx + qy*qy);
    }
    if (tid == 9) {
#pragma unroll
        for (int k = 0; k < 3; k++) {
            s_x[k]  = x_in[b*3+k];
            s_xd[k] = xd_in[b*3+k];
            s_om[k] = om_in[b*3+k];
        }
    }
    __syncthreads();

    // ------------------ Phase 0b: warp 0 only, overlapped with phase 1 ----
    if (tid < 32) {
        float m[D_];
        float tm = BODY_MASS;
#pragma unroll
        for (int d = 0; d < D_; d++) { m[d] = dpm_in[d]; tm += m[d]; }
        float cg0 = 0.f, cg1 = 0.f, cg2 = 0.f;
#pragma unroll
        for (int d = 0; d < D_; d++) {
            cg0 += s_cogl[d][0] * m[d];
            cg1 += s_cogl[d][1] * m[d];
            cg2 += s_cogl[d][2] * m[d];
        }
        const float bc0 = bcog_in[0], bc1 = bcog_in[1], bc2 = bcog_in[2];
        const float itm = 1.0f / tm;
        cg0 = (cg0 + BODY_MASS*bc0) * itm;
        cg1 = (cg1 + BODY_MASS*bc1) * itm;
        cg2 = (cg2 + BODY_MASS*bc2) * itm;

        if (tid < 24) {
            const int d = tid / 3, k = tid - 3*(tid/3);
            s_thr[d][k] = sR[k*3+0]*s_tl[d][0] + sR[k*3+1]*s_tl[d][1] + sR[k*3+2]*s_tl[d][2];
        }
        if (tid < 9) {
            const int r = tid / 3, c = tid - 3*(tid/3);
            float Iv = binert_in[tid];
#pragma unroll
            for (int d = 0; d < D_; d++) {
                const float ddx = s_cogl[d][0]-cg0, ddy = s_cogl[d][1]-cg1, ddz = s_cogl[d][2]-cg2;
                const float s2 = ddx*ddx + ddy*ddy + ddz*ddz;
                const float er = (r==0)?ddx:(r==1)?ddy:ddz;
                const float ec = (c==0)?ddx:(c==1)?ddy:ddz;
                Iv += s_rotI[d][tid] + m[d]*(((r==c)?s2:0.0f) - er*ec);
            }
            {
                const float ddx = bc0-cg0, ddy = bc1-cg1, ddz = bc2-cg2;
                const float s2 = ddx*ddx + ddy*ddy + ddz*ddz;
                const float er = (r==0)?ddx:(r==1)?ddy:ddz;
                const float ec = (c==0)?ddx:(c==1)?ddy:ddz;
                Iv += BODY_MASS*(((r==c)?s2:0.0f) - er*ec);
            }
            s_Iov[tid] = Iv;
        }
        if (tid >= 9 && tid < 12) {
            const int k = tid - 9;
            s_gcog[k] = sR[k*3+0]*cg0 + sR[k*3+1]*cg1 + sR[k*3+2]*cg2 + s_x[k];
        }
        if (tid >= 12 && tid < 15) {
            const int k = tid - 12;
            s_gdd[k] = sR[k*3+0]*ddir_in[0] + sR[k*3+1]*ddir_in[1] + sR[k*3+2]*ddir_in[2];
        }
        if (tid == 15) s_tm = tm;
        __syncwarp();
        if (tid < 9) {
            const int r = tid / 3, c = tid - 3*(tid/3);
            s_M9[tid] = sR[r*3+0]*s_Iov[c] + sR[r*3+1]*s_Iov[3+c] + sR[r*3+2]*s_Iov[6+c];
        }
        __syncwarp();
        if (tid < 9) {
            const int r = tid / 3, c = tid - 3*(tid/3);
            s_inertia[tid] = s_M9[r*3+0]*sR[c*3+0] + s_M9[r*3+1]*sR[c*3+1] + s_M9[r*3+2]*sR[c*3+2];
        }
    }

    // ------------------ Phase 1: points, terrain sample ------------------
    // Reordered: issue all 12 gathers immediately after address math; do the
    // rp smem/global stores inside the load-latency shadow, then consume.
    const float* __restrict__ zg  = zg_in  + (size_t)b * (H_*W_);
    const float* __restrict__ zgx = zgg_in + (size_t)b * (2*H_*W_);
    const float* __restrict__ zgy = zgx + H_*W_;

    float icsum = 0.0f;
#pragma unroll
    for (int k = 0; k < NPTS/NTHREADS; k++) {
        const int i = tid + k * NTHREADS;
        const int d = i >> 7;
        const float* jl = jlp_in + (size_t)i * 3;
        const float jx = jl[0], jy = jl[1], jz = jl[2];
        const float c = s_c[d], s = s_sn[d];
        const float plx =  c*jx + s*jz + s_jp[d][0];
        const float ply =  jy          + s_jp[d][1];
        const float plz = -s*jx + c*jz + s_jp[d][2];
        const float rx = sR[0]*plx + sR[1]*ply + sR[2]*plz + s_x[0];
        const float ry = sR[3]*plx + sR[4]*ply + sR[5]*plz + s_x[1];
        const float rz = sR[6]*plx + sR[7]*ply + sR[8]*plz + s_x[2];

        float u = (rx + MAX_COORD) * UV_SCALE;
        float v = (ry + MAX_COORD) * UV_SCALE;
        u = fminf(fmaxf(u, 0.0f), (float)(W_-1) - 1e-5f);
        v = fminf(fmaxf(v, 0.0f), (float)(H_-1) - 1e-5f);
        const int u0 = (int)floorf(u), v0 = (int)floorf(v);
        const float fu = u - (float)u0, fv = v - (float)v0;
        const int i00 = v0*W_ + u0;
        const int i10 = i00 + W_;

        // issue all 12 gathers first
        const float z00 = __ldg(zg + i00),  z01 = __ldg(zg + i00 + 1);
        const float z10 = __ldg(zg + i10),  z11 = __ldg(zg + i10 + 1);
        const float x00 = __ldg(zgx + i00), x01 = __ldg(zgx + i00 + 1);
        const float x10 = __ldg(zgx + i10), x11 = __ldg(zgx + i10 + 1);
        const float y00 = __ldg(zgy + i00), y01 = __ldg(zgy + i00 + 1);
        const float y10 = __ldg(zgy + i10), y11 = __ldg(zgy + i10 + 1);

        // work inside the load shadow: stage rp, write rp out
        s_rp[0][i] = rx; s_rp[1][i] = ry; s_rp[2][i] = rz;
        const size_t p3 = ((size_t)b * NPTS + i) * 3;
        out[OFF_RP + p3 + 0] = rx;
        out[OFF_RP + p3 + 1] = ry;
        out[OFF_RP + p3 + 2] = rz;

        // consume gathers
        const float gu = 1.0f - fu, gv = 1.0f - fv;
        const float zs = (z00*gu + z01*fu)*gv + (z10*gu + z11*fu)*fv;
        const float gx = (x00*gu + x01*fu)*gv + (x10*gu + x11*fu)*fv;
        const float gy = (y00*gu + y01*fu)*gv + (y10*gu + y11*fu)*fv;

        // 1/(sqrt(ss)+1e-8) ≈ rsqrt(ss + 1e-16)  (rel diff ~1e-8)
        const float inv = rsqrtf(gx*gx + gy*gy + 1.0f + 1e-16f);
        const float dh = (rz - zs) * inv;           // nz == inv
        const float ic = 0.5f * (1.0f + tanh_fast(dh * IC_SCALE));

        s_gx[i] = gx; s_gy[i] = gy; s_dh[i] = dh;
        icsum += ic;
        out[OFF_IC + (size_t)b*NPTS + i] = ic;
    }

    {   // contact-count partials
        const float ws = warp_sum(icsum);
        const int lane = tid & 31;
        if (lane == 0) s_red[w] = ws;
    }
    __syncthreads();

    // all threads compute nc redundantly (one barrier total)
    float nc = 0.0f;
#pragma unroll
    for (int w8 = 0; w8 < 8; w8++) nc += s_red[w8];
    nc = fmaxf(nc, 1.0f);
    const float inv_nc = __fdividef(1.0f, nc);
    const float kd = sqrtf(s_tm * K_STIFF * inv_nc);   // DAMPING_ALPHA*2 = 1

    // ------------------ Phase 2: forces ------------------
    const float gddx = s_gdd[0], gddy = s_gdd[1], gddz = s_gdd[2];
    const float ox = s_om[0], oy = s_om[1], oz = s_om[2];
    const float gc0 = s_gcog[0], gc1 = s_gcog[1], gc2 = s_gcog[2];
    const float xd0 = s_xd[0], xd1 = s_xd[1], xd2 = s_xd[2];
    float asx=0.f, asy=0.f, asz=0.f, tqx=0.f, tqy=0.f, tqz=0.f;

#pragma unroll
    for (int k = 0; k < NPTS/NTHREADS; k++) {
        const int i = tid + k * NTHREADS;
        const int d = i >> 7;
        // recompute n, ic from staged {gx, gy, dh}
        const float gx = s_gx[i], gy = s_gy[i], dh = s_dh[i];
        const float invn = rsqrtf(gx*gx + gy*gy + 1.0f + 1e-16f);
        const float nx = -gx*invn, ny = -gy*invn, nz = invn;
        const float ic = 0.5f * (1.0f + tanh_fast(dh * IC_SCALE));

        const float ccx = s_rp[0][i] - gc0;
        const float ccy = s_rp[1][i] - gc1;
        const float ccz = s_rp[2][i] - gc2;
        const float vx = xd0 + oy*ccz - oz*ccy;
        const float vy = xd1 + oz*ccx - ox*ccz;
        const float vz = xd2 + ox*ccy - oy*ccx;
        const float xdn = vx*nx + vy*ny + vz*nz;
        const float coef = -(K_STIFF * (dh*ic) + kd * xdn) * ic * inv_nc;
        const float fsx = coef*nx, fsy = coef*ny, fsz = coef*nz;
        const float Nmag = fabsf(coef);       // ||coef * n||, |n| == 1

        const float gdn = gddx*nx + gddy*ny + gddz*nz;
        float fwx = gddx - gdn*nx, fwy = gddy - gdn*ny, fwz = gddz - gdn*nz;
        {
            const float iv = rsqrtf(fwx*fwx + fwy*fwy + fwz*fwz + 1e-16f);
            fwx *= iv; fwy *= iv; fwz *= iv;
        }
        float ltx = fwy*nz - fwz*ny;
        float lty = fwz*nx - fwx*nz;
        float ltz = fwx*ny - fwy*nx;
        {
            const float iv = rsqrtf(ltx*ltx + lty*lty + ltz*ltz + 1e-16f);
            ltx *= iv; lty *= iv; ltz *= iv;
        }
        const float thx = s_thr[d][0], thy = s_thr[d][1], thz = s_thr[d][2];
        const float dvx = thx - vx;
        const float dvy = thy - vy;
        const float dvz = thz - vz;
        const float dvn = dvx*nx + dvy*ny + dvz*nz;
        const float tx = tanh_fast(dvx - dvn*nx);
        const float ty = tanh_fast(dvy - dvn*ny);
        const float tz = tanh_fast(dvz - dvn*nz);
        const float lon = tx*fwx + ty*fwy + tz*fwz;
        const float lat = tx*ltx + ty*lty + tz*ltz;
        const float c1 = K_LON * Nmag * lon;
        const float c2 = K_LAT * Nmag * lat;
        const float ffx = c1*fwx + c2*ltx;
        const float ffy = c1*fwy + c2*lty;
        const float ffz = c1*fwz + c2*ltz;

        const float ax = fsx + ffx, ay = fsy + ffy, az = fsz + ffz;
        asx += ax; asy += ay; asz += az;
        tqx += ccy*az - ccz*ay;
        tqy += ccz*ax - ccx*az;
        tqz += ccx*ay - ccy*ax;

        const size_t p3 = ((size_t)b * NPTS + i) * 3;
        out[OFF_FS + p3 + 0] = fsx;
        out[OFF_FS + p3 + 1] = fsy;
        out[OFF_FS + p3 + 2] = fsz;
        out[OFF_FF + p3 + 0] = ffx;
        out[OFF_FF + p3 + 1] = ffy;
        out[OFF_FF + p3 + 2] = ffz;
        out[OFF_THR + p3 + 0] = thx;
        out[OFF_THR + p3 + 1] = thy;
        out[OFF_THR + p3 + 2] = thz;
    }

    {   // reduce 6 sums
        float r[6] = {asx, asy, asz, tqx, tqy, tqz};
        const int lane = tid & 31;
#pragma unroll
        for (int j = 0; j < 6; j++) {
            const float ws = warp_sum(r[j]);
            if (lane == 0) s_red[j*8 + w] = ws;
        }
    }
    __syncthreads();

    // ------------------ Phase 3: solve + integrate ------------------
    if (tid == 0) {
        float as0 = 0.f, as1 = 0.f, as2 = 0.f, t0 = 0.f, t1 = 0.f, t2 = 0.f;
#pragma unroll
        for (int w8 = 0; w8 < 8; w8++) {
            as0 += s_red[0*8 + w8]; as1 += s_red[1*8 + w8]; as2 += s_red[2*8 + w8];
            t0  += s_red[3*8 + w8]; t1  += s_red[4*8 + w8]; t2  += s_red[5*8 + w8];
        }
        const float tqcx = fminf(fmaxf(t0, -TORQUE_LIM), TORQUE_LIM);
        const float tqcy = fminf(fmaxf(t1, -TORQUE_LIM), TORQUE_LIM);
        const float tqcz = fminf(fmaxf(t2, -TORQUE_LIM), TORQUE_LIM);
        out[OFF_TQ + (size_t)b*3 + 0] = tqcx;
        out[OFF_TQ + (size_t)b*3 + 1] = tqcy;
        out[OFF_TQ + (size_t)b*3 + 2] = tqcz;

        const double a00=s_inertia[0], a01=s_inertia[1], a02=s_inertia[2];
        const double a10=s_inertia[3], a11=s_inertia[4], a12=s_inertia[5];
        const double a20=s_inertia[6], a21=s_inertia[7], a22=s_inertia[8];
        const double bx=tqcx, by=tqcy, bz=tqcz;
        const double c00 = a11*a22 - a12*a21;
        const double c01 = a10*a22 - a12*a20;
        const double c02 = a10*a21 - a11*a20;
        const double det = a00*c00 - a01*c01 + a02*c02;
        const double inv = 1.0/det;
        const double odx = (bx*c00 - a01*(by*a22 - a12*bz) + a02*(by*a21 - a11*bz)) * inv;
        const double ody = (a00*(by*a22 - a12*bz) - bx*c01 + a02*(a10*bz - by*a20)) * inv;
        const double odz = (a00*(a11*bz - by*a21) - a01*(a10*bz - by*a20) + bx*c02) * inv;
        const float odxf=(float)odx, odyf=(float)ody, odzf=(float)odz;
        out[OFF_OMD + (size_t)b*3 + 0] = odxf;
        out[OFF_OMD + (size_t)b*3 + 1] = odyf;
        out[OFF_OMD + (size_t)b*3 + 2] = odzf;

        const float itm = __fdividef(1.0f, s_tm);
        const float xddx = as0 * itm;
        const float xddy = as1 * itm;
        const float xddz = (as2 - s_tm*GRAVITY) * itm;
        out[OFF_XDD + (size_t)b*3 + 0] = xddx;
        out[OFF_XDD + (size_t)b*3 + 1] = xddy;
        out[OFF_XDD + (size_t)b*3 + 2] = xddz;

        const float nxd0 = s_xd[0] + xddx*DT;
        const float nxd1 = s_xd[1] + xddy*DT;
        const float nxd2 = s_xd[2] + xddz*DT;
        out[OFF_NXD + (size_t)b*3 + 0] = nxd0;
        out[OFF_NXD + (size_t)b*3 + 1] = nxd1;
        out[OFF_NXD + (size_t)b*3 + 2] = nxd2;
        out[OFF_NX + (size_t)b*3 + 0] = s_x[0] + nxd0*DT;
        out[OFF_NX + (size_t)b*3 + 1] = s_x[1] + nxd1*DT;
        out[OFF_NX + (size_t)b*3 + 2] = s_x[2] + nxd2*DT;

        const float no0 = s_om[0] + odxf*DT;
        const float no1 = s_om[1] + odyf*DT;
        const float no2 = s_om[2] + odzf*DT;
        out[OFF_NOM + (size_t)b*3 + 0] = no0;
        out[OFF_NOM + (size_t)b*3 + 1] = no1;
        out[OFF_NOM + (size_t)b*3 + 2] = no2;

        const float aw = q_in[b*4+0], axq = q_in[b*4+1], ayq = q_in[b*4+2], azq = q_in[b*4+3];
        const float h = 0.5f * DT;
        const float dqw = h * (-(axq*no0 + ayq*no1 + azq*no2));
        const float dqx = h * ( aw*no0 + ayq*no2 - azq*no1);
        const float dqy = h * ( aw*no1 - axq*no2 + azq*no0);
        const float dqz = h * ( aw*no2 + axq*no1 - ayq*no0);
        const float nqw = aw + dqw, nqx = axq + dqx, nqy = ayq + dqy, nqz = azq + dqz;
        const float qn = sqrtf(nqw*nqw + nqx*nqx + nqy*nqy + nqz*nqz);
        const float qi = __fdividef(1.0f, qn + 1e-8f);
        out[OFF_NQ + (size_t)b*4 + 0] = nqw*qi;
        out[OFF_NQ + (size_t)b*4 + 1] = nqx*qi;
        out[OFF_NQ + (size_t)b*4 + 2] = nqy*qi;
        out[OFF_NQ + (size_t)b*4 + 3] = nqz*qi;
    }
}

extern "C" void kernel_launch(void* const* d_in, const int* in_sizes, int n_in,
                              void* d_out, int out_size)
{
    phys_kernel<<<B_, NTHREADS>>>(
        (const float*)d_in[0],  (const float*)d_in[1],  (const float*)d_in[2],
        (const float*)d_in[3],  (const float*)d_in[4],  (const float*)d_in[5],
        (const float*)d_in[6],  (const float*)d_in[7],  (const float*)d_in[8],
        (const float*)d_in[9],  (const float*)d_in[10], (const float*)d_in[11],
        (const float*)d_in[12], (const float*)d_in[13], (const float*)d_in[14],
        (const float*)d_in[15], (float*)d_out);
}

// round 15
// speedup vs baseline: 1.0667x; 1.0175x over previous
#include <cuda_runtime.h>
#include <math.h>

#define B_    1024
#define D_    8
#define P_    128
#define NPTS  1024
#define H_    256
#define W_    256
#define NTHREADS 256

#define GRAVITY     9.8f
#define DT          0.01f
#define TORQUE_LIM  200.0f
#define K_STIFF     5000.0f
#define K_LON       0.5f
#define K_LAT       0.5f
#define BODY_MASS   40.0f
#define MAX_COORD   6.4f
#define IC_SCALE    (-57.73502691896258f)   /* -sqrt(3)/SIGMA */
#define UV_SCALE    19.921875f              /* (W-1)/(2*MAX_COORD) */

// output offsets (floats)
#define OFF_NX   0
#define OFF_NXD  3072
#define OFF_NQ   6144
#define OFF_NOM  10240
#define OFF_NTH  13312
#define OFF_XDD  21504
#define OFF_OMD  24576
#define OFF_THD  27648
#define OFF_FS   35840
#define OFF_FF   3181568
#define OFF_IC   6327296
#define OFF_TQ   7375872
#define OFF_RP   7378944
#define OFF_THR  10524672

__device__ __forceinline__ float warp_sum(float v) {
#pragma unroll
    for (int o = 16; o; o >>= 1) v += __shfl_xor_sync(0xffffffffu, v, o);
    return v;
}

__device__ __forceinline__ float tanh_fast(float x) {
    float y;
    asm("tanh.approx.f32 %0, %1;" : "=f"(y) : "f"(x));
    return y;
}

__global__ __launch_bounds__(NTHREADS, 4)
void phys_kernel(const float* __restrict__ x_in,
                 const float* __restrict__ xd_in,
                 const float* __restrict__ q_in,
                 const float* __restrict__ om_in,
                 const float* __restrict__ th_in,
                 const float* __restrict__ ctrl_in,
                 const float* __restrict__ zg_in,
                 const float* __restrict__ zgg_in,
                 const float* __restrict__ jp_in,
                 const float* __restrict__ jlp_in,
                 const float* __restrict__ jlc_in,
                 const float* __restrict__ dpi_in,
                 const float* __restrict__ dpm_in,
                 const float* __restrict__ bcog_in,
                 const float* __restrict__ binert_in,
                 const float* __restrict__ ddir_in,
                 float* __restrict__ out)
{
    const int b   = blockIdx.x;
    const int tid = threadIdx.x;
    const int w   = tid >> 5;

    // per-point staging (26 KB total smem): rp(3), gx, gy, dh
    __shared__ float s_rp[3][NPTS];
    __shared__ float s_gx[NPTS], s_gy[NPTS], s_dh[NPTS];

    __shared__ float sR[9];
    __shared__ float s_c[D_], s_sn[D_];
    __shared__ float s_jp[D_][3];
    __shared__ float s_cogl[D_][3];
    __shared__ float s_rotI[D_][9];
    __shared__ float s_tl[D_][3];
    __shared__ float s_thr[D_][3];
    __shared__ float s_Iov[9], s_M9[9];
    __shared__ float s_gcog[3], s_gdd[3], s_inertia[9];
    __shared__ float s_x[3], s_xd[3], s_om[3];
    __shared__ float s_tm;
    __shared__ float s_red[48];

    // ------------------ Phase 0a: per-part prep ------------------
    if (tid < D_) {
        const int d = tid;
        const float th = th_in[b * D_ + d];
        const float c = cosf(th), s = sinf(th);
        s_c[d] = c; s_sn[d] = s;
        const float jpx = jp_in[d*3+0], jpy = jp_in[d*3+1], jpz = jp_in[d*3+2];
        s_jp[d][0] = jpx; s_jp[d][1] = jpy; s_jp[d][2] = jpz;
        const float lx = jlc_in[d*3+0], ly = jlc_in[d*3+1], lz = jlc_in[d*3+2];
        s_cogl[d][0] =  c*lx + s*lz + jpx;
        s_cogl[d][1] =  ly + jpy;
        s_cogl[d][2] = -s*lx + c*lz + jpz;
        float I9[9];
#pragma unroll
        for (int k = 0; k < 9; k++) I9[k] = dpi_in[d*9 + k];
        float M[9];
        M[0] =  c*I9[0] + s*I9[6];  M[1] =  c*I9[1] + s*I9[7];  M[2] =  c*I9[2] + s*I9[8];
        M[3] =  I9[3];              M[4] =  I9[4];              M[5] =  I9[5];
        M[6] = -s*I9[0] + c*I9[6];  M[7] = -s*I9[1] + c*I9[7];  M[8] = -s*I9[2] + c*I9[8];
#pragma unroll
        for (int r = 0; r < 3; r++) {
            s_rotI[d][r*3+0] =  M[r*3+0]*c + M[r*3+2]*s;
            s_rotI[d][r*3+1] =  M[r*3+1];
            s_rotI[d][r*3+2] = -M[r*3+0]*s + M[r*3+2]*c;
        }
        const float dx = ddir_in[0], dy = ddir_in[1], dz = ddir_in[2];
        const float vc = ctrl_in[b*2*D_ + d];
        s_tl[d][0] = ( c*dx + s*dz) * vc;
        s_tl[d][1] = ( dy          ) * vc;
        s_tl[d][2] = (-s*dx + c*dz) * vc;
        float td = ctrl_in[b*2*D_ + D_ + d];
        td = fminf(fmaxf(td, -0.5f), 0.5f);
        out[OFF_THD + (size_t)b*D_ + d] = td;
        float nth = th + td * DT;
        out[OFF_NTH + (size_t)b*D_ + d] = fminf(fmaxf(nth, -1.0f), 1.0f);
    }
    if (tid == 8) {
        const float qw = q_in[b*4+0], qx = q_in[b*4+1], qy = q_in[b*4+2], qz = q_in[b*4+3];
        sR[0] = 1.0f - 2.0f*(qy*qy + qz*qz);
        sR[1] = 2.0f*(qx*qy - qw*qz);
        sR[2] = 2.0f*(qx*qz + qw*qy);
        sR[3] = 2.0f*(qx*qy + qw*qz);
        sR[4] = 1.0f - 2.0f*(qx*qx + qz*qz);
        sR[5] = 2.0f*(qy*qz - qw*qx);
        sR[6] = 2.0f*(qx*qz - qw*qy);
        sR[7] = 2.0f*(qy*qz + qw*qx);
        sR[8] = 1.0f - 2.0f*(qx*qx + qy*qy);
    }
    if (tid == 9) {
#pragma unroll
        for (int k = 0; k < 3; k++) {
            s_x[k]  = x_in[b*3+k];
            s_xd[k] = xd_in[b*3+k];
            s_om[k] = om_in[b*3+k];
        }
    }
    __syncthreads();

    // ------------------ Phase 0b: warp 0 only, overlapped with phase 1 ----
    if (tid < 32) {
        float m[D_];
        float tm = BODY_MASS;
#pragma unroll
        for (int d = 0; d < D_; d++) { m[d] = dpm_in[d]; tm += m[d]; }
        float cg0 = 0.f, cg1 = 0.f, cg2 = 0.f;
#pragma unroll
        for (int d = 0; d < D_; d++) {
            cg0 += s_cogl[d][0] * m[d];
            cg1 += s_cogl[d][1] * m[d];
            cg2 += s_cogl[d][2] * m[d];
        }
        const float bc0 = bcog_in[0], bc1 = bcog_in[1], bc2 = bcog_in[2];
        const float itm = 1.0f / tm;
        cg0 = (cg0 + BODY_MASS*bc0) * itm;
        cg1 = (cg1 + BODY_MASS*bc1) * itm;
        cg2 = (cg2 + BODY_MASS*bc2) * itm;

        if (tid < 24) {
            const int d = tid / 3, k = tid - 3*(tid/3);
            s_thr[d][k] = sR[k*3+0]*s_tl[d][0] + sR[k*3+1]*s_tl[d][1] + sR[k*3+2]*s_tl[d][2];
        }
        if (tid < 9) {
            const int r = tid / 3, c = tid - 3*(tid/3);
            float Iv = binert_in[tid];
#pragma unroll
            for (int d = 0; d < D_; d++) {
                const float ddx = s_cogl[d][0]-cg0, ddy = s_cogl[d][1]-cg1, ddz = s_cogl[d][2]-cg2;
                const float s2 = ddx*ddx + ddy*ddy + ddz*ddz;
                const float er = (r==0)?ddx:(r==1)?ddy:ddz;
                const float ec = (c==0)?ddx:(c==1)?ddy:ddz;
                Iv += s_rotI[d][tid] + m[d]*(((r==c)?s2:0.0f) - er*ec);
            }
            {
                const float ddx = bc0-cg0, ddy = bc1-cg1, ddz = bc2-cg2;
                const float s2 = ddx*ddx + ddy*ddy + ddz*ddz;
                const float er = (r==0)?ddx:(r==1)?ddy:ddz;
                const float ec = (c==0)?ddx:(c==1)?ddy:ddz;
                Iv += BODY_MASS*(((r==c)?s2:0.0f) - er*ec);
            }
            s_Iov[tid] = Iv;
        }
        if (tid >= 9 && tid < 12) {
            const int k = tid - 9;
            s_gcog[k] = sR[k*3+0]*cg0 + sR[k*3+1]*cg1 + sR[k*3+2]*cg2 + s_x[k];
        }
        if (tid >= 12 && tid < 15) {
            const int k = tid - 12;
            s_gdd[k] = sR[k*3+0]*ddir_in[0] + sR[k*3+1]*ddir_in[1] + sR[k*3+2]*ddir_in[2];
        }
        if (tid == 15) s_tm = tm;
        __syncwarp();
        if (tid < 9) {
            const int r = tid / 3, c = tid - 3*(tid/3);
            s_M9[tid] = sR[r*3+0]*s_Iov[c] + sR[r*3+1]*s_Iov[3+c] + sR[r*3+2]*s_Iov[6+c];
        }
        __syncwarp();
        if (tid < 9) {
            const int r = tid / 3, c = tid - 3*(tid/3);
            s_inertia[tid] = s_M9[r*3+0]*sR[c*3+0] + s_M9[r*3+1]*sR[c*3+1] + s_M9[r*3+2]*sR[c*3+2];
        }
    }

    // ------------------ Phase 1: points, terrain sample ------------------
    const float* __restrict__ zg  = zg_in  + (size_t)b * (H_*W_);
    const float* __restrict__ zgx = zgg_in + (size_t)b * (2*H_*W_);
    const float* __restrict__ zgy = zgx + H_*W_;

    float icsum = 0.0f;
#pragma unroll
    for (int k = 0; k < NPTS/NTHREADS; k++) {
        const int i = tid + k * NTHREADS;
        const int d = i >> 7;
        const float* jl = jlp_in + (size_t)i * 3;
        const float jx = jl[0], jy = jl[1], jz = jl[2];
        const float c = s_c[d], s = s_sn[d];
        const float plx =  c*jx + s*jz + s_jp[d][0];
        const float ply =  jy          + s_jp[d][1];
        const float plz = -s*jx + c*jz + s_jp[d][2];
        const float rx = sR[0]*plx + sR[1]*ply + sR[2]*plz + s_x[0];
        const float ry = sR[3]*plx + sR[4]*ply + sR[5]*plz + s_x[1];
        const float rz = sR[6]*plx + sR[7]*ply + sR[8]*plz + s_x[2];

        float u = (rx + MAX_COORD) * UV_SCALE;
        float v = (ry + MAX_COORD) * UV_SCALE;
        u = fminf(fmaxf(u, 0.0f), (float)(W_-1) - 1e-5f);
        v = fminf(fmaxf(v, 0.0f), (float)(H_-1) - 1e-5f);
        const int u0 = (int)floorf(u), v0 = (int)floorf(v);
        const float fu = u - (float)u0, fv = v - (float)v0;
        const int i00 = v0*W_ + u0;
        const int i10 = i00 + W_;

        // issue all 12 gathers first
        const float z00 = __ldg(zg + i00),  z01 = __ldg(zg + i00 + 1);
        const float z10 = __ldg(zg + i10),  z11 = __ldg(zg + i10 + 1);
        const float x00 = __ldg(zgx + i00), x01 = __ldg(zgx + i00 + 1);
        const float x10 = __ldg(zgx + i10), x11 = __ldg(zgx + i10 + 1);
        const float y00 = __ldg(zgy + i00), y01 = __ldg(zgy + i00 + 1);
        const float y10 = __ldg(zgy + i10), y11 = __ldg(zgy + i10 + 1);

        // work inside the load shadow: stage rp, write rp out
        s_rp[0][i] = rx; s_rp[1][i] = ry; s_rp[2][i] = rz;
        const size_t p3 = ((size_t)b * NPTS + i) * 3;
        out[OFF_RP + p3 + 0] = rx;
        out[OFF_RP + p3 + 1] = ry;
        out[OFF_RP + p3 + 2] = rz;

        // consume gathers
        const float gu = 1.0f - fu, gv = 1.0f - fv;
        const float zs = (z00*gu + z01*fu)*gv + (z10*gu + z11*fu)*fv;
        const float gx = (x00*gu + x01*fu)*gv + (x10*gu + x11*fu)*fv;
        const float gy = (y00*gu + y01*fu)*gv + (y10*gu + y11*fu)*fv;

        // 1/(sqrt(ss)+1e-8) ≈ rsqrt(ss + 1e-16)  (rel diff ~1e-8)
        const float inv = rsqrtf(gx*gx + gy*gy + 1.0f + 1e-16f);
        const float dh = (rz - zs) * inv;           // nz == inv
        const float ic = 0.5f * (1.0f + tanh_fast(dh * IC_SCALE));

        s_gx[i] = gx; s_gy[i] = gy; s_dh[i] = dh;
        icsum += ic;
        out[OFF_IC + (size_t)b*NPTS + i] = ic;
    }

    {   // contact-count partials
        const float ws = warp_sum(icsum);
        const int lane = tid & 31;
        if (lane == 0) s_red[w] = ws;
    }
    __syncthreads();

    // all threads compute nc redundantly (one barrier total)
    float nc = 0.0f;
#pragma unroll
    for (int w8 = 0; w8 < 8; w8++) nc += s_red[w8];
    nc = fmaxf(nc, 1.0f);
    const float inv_nc = __fdividef(1.0f, nc);
    const float kd = sqrtf(s_tm * K_STIFF * inv_nc);   // DAMPING_ALPHA*2 = 1

    // ------------------ Phase 2: forces ------------------
    const float gddx = s_gdd[0], gddy = s_gdd[1], gddz = s_gdd[2];
    const float ox = s_om[0], oy = s_om[1], oz = s_om[2];
    const float gc0 = s_gcog[0], gc1 = s_gcog[1], gc2 = s_gcog[2];
    const float xd0 = s_xd[0], xd1 = s_xd[1], xd2 = s_xd[2];
    float asx=0.f, asy=0.f, asz=0.f, tqx=0.f, tqy=0.f, tqz=0.f;

#pragma unroll
    for (int k = 0; k < NPTS/NTHREADS; k++) {
        const int i = tid + k * NTHREADS;
        const int d = i >> 7;
        // recompute n, ic from staged {gx, gy, dh}
        const float gx = s_gx[i], gy = s_gy[i], dh = s_dh[i];
        const float invn = rsqrtf(gx*gx + gy*gy + 1.0f + 1e-16f);
        const float nx = -gx*invn, ny = -gy*invn, nz = invn;
        const float ic = 0.5f * (1.0f + tanh_fast(dh * IC_SCALE));

        const float ccx = s_rp[0][i] - gc0;
        const float ccy = s_rp[1][i] - gc1;
        const float ccz = s_rp[2][i] - gc2;
        const float vx = xd0 + oy*ccz - oz*ccy;
        const float vy = xd1 + oz*ccx - ox*ccz;
        const float vz = xd2 + ox*ccy - oy*ccx;
        const float xdn = vx*nx + vy*ny + vz*nz;
        const float coef = -(K_STIFF * (dh*ic) + kd * xdn) * ic * inv_nc;
        const float fsx = coef*nx, fsy = coef*ny, fsz = coef*nz;
        const float Nmag = fabsf(coef);       // ||coef * n||, |n| == 1

        const float gdn = gddx*nx + gddy*ny + gddz*nz;
        float fwx = gddx - gdn*nx, fwy = gddy - gdn*ny, fwz = gddz - gdn*nz;
        {
            const float iv = rsqrtf(fwx*fwx + fwy*fwy + fwz*fwz + 1e-16f);
            fwx *= iv; fwy *= iv; fwz *= iv;
        }
        // lat = cross(fwd, n): |fwd|=1, |n|=1, fwd ⟂ n  =>  |cross| = 1
        // (second normalization is redundant to ~1e-7)
        const float ltx = fwy*nz - fwz*ny;
        const float lty = fwz*nx - fwx*nz;
        const float ltz = fwx*ny - fwy*nx;

        const float thx = s_thr[d][0], thy = s_thr[d][1], thz = s_thr[d][2];
        const float dvx = thx - vx;
        const float dvy = thy - vy;
        const float dvz = thz - vz;
        const float dvn = dvx*nx + dvy*ny + dvz*nz;
        const float tx = tanh_fast(dvx - dvn*nx);
        const float ty = tanh_fast(dvy - dvn*ny);
        const float tz = tanh_fast(dvz - dvn*nz);
        const float lon = tx*fwx + ty*fwy + tz*fwz;
        const float lat = tx*ltx + ty*lty + tz*ltz;
        const float c1 = K_LON * Nmag * lon;
        const float c2 = K_LAT * Nmag * lat;
        const float ffx = c1*fwx + c2*ltx;
        const float ffy = c1*fwy + c2*lty;
        const float ffz = c1*fwz + c2*ltz;

        const float ax = fsx + ffx, ay = fsy + ffy, az = fsz + ffz;
        asx += ax; asy += ay; asz += az;
        tqx += ccy*az - ccz*ay;
        tqy += ccz*ax - ccx*az;
        tqz += ccx*ay - ccy*ax;

        const size_t p3 = ((size_t)b * NPTS + i) * 3;
        out[OFF_FS + p3 + 0] = fsx;
        out[OFF_FS + p3 + 1] = fsy;
        out[OFF_FS + p3 + 2] = fsz;
        out[OFF_FF + p3 + 0] = ffx;
        out[OFF_FF + p3 + 1] = ffy;
        out[OFF_FF + p3 + 2] = ffz;
        out[OFF_THR + p3 + 0] = thx;
        out[OFF_THR + p3 + 1] = thy;
        out[OFF_THR + p3 + 2] = thz;
    }

    {   // reduce 6 sums
        float r[6] = {asx, asy, asz, tqx, tqy, tqz};
        const int lane = tid & 31;
#pragma unroll
        for (int j = 0; j < 6; j++) {
            const float ws = warp_sum(r[j]);
            if (lane == 0) s_red[j*8 + w] = ws;
        }
    }
    __syncthreads();

    // ------------------ Phase 3: solve + integrate ------------------
    if (tid == 0) {
        float as0 = 0.f, as1 = 0.f, as2 = 0.f, t0 = 0.f, t1 = 0.f, t2 = 0.f;
#pragma unroll
        for (int w8 = 0; w8 < 8; w8++) {
            as0 += s_red[0*8 + w8]; as1 += s_red[1*8 + w8]; as2 += s_red[2*8 + w8];
            t0  += s_red[3*8 + w8]; t1  += s_red[4*8 + w8]; t2  += s_red[5*8 + w8];
        }
        const float tqcx = fminf(fmaxf(t0, -TORQUE_LIM), TORQUE_LIM);
        const float tqcy = fminf(fmaxf(t1, -TORQUE_LIM), TORQUE_LIM);
        const float tqcz = fminf(fmaxf(t2, -TORQUE_LIM), TORQUE_LIM);
        out[OFF_TQ + (size_t)b*3 + 0] = tqcx;
        out[OFF_TQ + (size_t)b*3 + 1] = tqcy;
        out[OFF_TQ + (size_t)b*3 + 2] = tqcz;

        const double a00=s_inertia[0], a01=s_inertia[1], a02=s_inertia[2];
        const double a10=s_inertia[3], a11=s_inertia[4], a12=s_inertia[5];
        const double a20=s_inertia[6], a21=s_inertia[7], a22=s_inertia[8];
        const double bx=tqcx, by=tqcy, bz=tqcz;
        const double c00 = a11*a22 - a12*a21;
        const double c01 = a10*a22 - a12*a20;
        const double c02 = a10*a21 - a11*a20;
        const double det = a00*c00 - a01*c01 + a02*c02;
        const double inv = 1.0/det;
        const double odx = (bx*c00 - a01*(by*a22 - a12*bz) + a02*(by*a21 - a11*bz)) * inv;
        const double ody = (a00*(by*a22 - a12*bz) - bx*c01 + a02*(a10*bz - by*a20)) * inv;
        const double odz = (a00*(a11*bz - by*a21) - a01*(a10*bz - by*a20) + bx*c02) * inv;
        const float odxf=(float)odx, odyf=(float)ody, odzf=(float)odz;
        out[OFF_OMD + (size_t)b*3 + 0] = odxf;
        out[OFF_OMD + (size_t)b*3 + 1] = odyf;
        out[OFF_OMD + (size_t)b*3 + 2] = odzf;

        const float itm = __fdividef(1.0f, s_tm);
        const float xddx = as0 * itm;
        const float xddy = as1 * itm;
        const float xddz = (as2 - s_tm*GRAVITY) * itm;
        out[OFF_XDD + (size_t)b*3 + 0] = xddx;
        out[OFF_XDD + (size_t)b*3 + 1] = xddy;
        out[OFF_XDD + (size_t)b*3 + 2] = xddz;

        const float nxd0 = s_xd[0] + xddx*DT;
        const float nxd1 = s_xd[1] + xddy*DT;
        const float nxd2 = s_xd[2] + xddz*DT;
        out[OFF_NXD + (size_t)b*3 + 0] = nxd0;
        out[OFF_NXD + (size_t)b*3 + 1] = nxd1;
        out[OFF_NXD + (size_t)b*3 + 2] = nxd2;
        out[OFF_NX + (size_t)b*3 + 0] = s_x[0] + nxd0*DT;
        out[OFF_NX + (size_t)b*3 + 1] = s_x[1] + nxd1*DT;
        out[OFF_NX + (size_t)b*3 + 2] = s_x[2] + nxd2*DT;

        const float no0 = s_om[0] + odxf*DT;
        const float no1 = s_om[1] + odyf*DT;
        const float no2 = s_om[2] + odzf*DT;
        out[OFF_NOM + (size_t)b*3 + 0] = no0;
        out[OFF_NOM + (size_t)b*3 + 1] = no1;
        out[OFF_NOM + (size_t)b*3 + 2] = no2;

        const float aw = q_in[b*4+0], axq = q_in[b*4+1], ayq = q_in[b*4+2], azq = q_in[b*4+3];
        const float h = 0.5f * DT;
        const float dqw = h * (-(axq*no0 + ayq*no1 + azq*no2));
        const float dqx = h * ( aw*no0 + ayq*no2 - azq*no1);
        const float dqy = h * ( aw*no1 - axq*no2 + azq*no0);
        const float dqz = h * ( aw*no2 + axq*no1 - ayq*no0);
        const float nqw = aw + dqw, nqx = axq + dqx, nqy = ayq + dqy, nqz = azq + dqz;
        const float qn = sqrtf(nqw*nqw + nqx*nqx + nqy*nqy + nqz*nqz);
        const float qi = __fdividef(1.0f, qn + 1e-8f);
        out[OFF_NQ + (size_t)b*4 + 0] = nqw*qi;
        out[OFF_NQ + (size_t)b*4 + 1] = nqx*qi;
        out[OFF_NQ + (size_t)b*4 + 2] = nqy*qi;
        out[OFF_NQ + (size_t)b*4 + 3] = nqz*qi;
    }
}

extern "C" void kernel_launch(void* const* d_in, const int* in_sizes, int n_in,
                              void* d_out, int out_size)
{
    phys_kernel<<<B_, NTHREADS>>>(
        (const float*)d_in[0],  (const float*)d_in[1],  (const float*)d_in[2],
        (const float*)d_in[3],  (const float*)d_in[4],  (const float*)d_in[5],
        (const float*)d_in[6],  (const float*)d_in[7],  (const float*)d_in[8],
        (const float*)d_in[9],  (const float*)d_in[10], (const float*)d_in[11],
        (const float*)d_in[12], (const float*)d_in[13], (const float*)d_in[14],
        (const float*)d_in[15], (float*)d_out);
}